// round 15
// baseline (speedup 1.0000x reference)
#include <cuda_runtime.h>

#define B_  2048
#define T_  512
#define D_  128
#define G3_ 192

typedef unsigned long long ull;

__device__ __align__(256) float g_gx[(size_t)T_ * B_ * G3_];  // [T][B][192]

__device__ __forceinline__ ull splat2(float x){ ull r; asm("mov.b64 %0, {%1, %1};" : "=l"(r) : "f"(x)); return r; }
__device__ __forceinline__ ull fma2(ull a, ull b, ull c){ ull d; asm("fma.rn.f32x2 %0, %1, %2, %3;" : "=l"(d) : "l"(a), "l"(b), "l"(c)); return d; }
__device__ __forceinline__ float2 u2f(ull v){ float2 f; asm("mov.b64 {%0, %1}, %2;" : "=f"(f.x), "=f"(f.y) : "l"(v)); return f; }
__device__ __forceinline__ ull f2u(float x, float y){ ull r; asm("mov.b64 %0, {%1, %2};" : "=l"(r) : "f"(x), "f"(y)); return r; }
__device__ __forceinline__ float sig_(float x){ return __fdividef(1.f, 1.f + __expf(-x)); }
__device__ __forceinline__ float tanh_(float x){ return 1.f - __fdividef(2.f, __expf(2.f*x) + 1.f); }

// ======================= Kernel A: feedforward ==============================
// gx[t][b][g] = Wih @ relu(W1 @ s + b1) + bih.  Block: 64 rows x 8 timesteps.
__global__ void __launch_bounds__(256) ff_kernel(
    const float* __restrict__ S, const float* __restrict__ W1,
    const float* __restrict__ b1, const float* __restrict__ Wih,
    const float* __restrict__ bih)
{
    extern __shared__ float sm[];
    float* W1T  = sm;            // [128][64]
    float* WihT = sm + 8192;     // [64][192]
    float* sS   = sm + 20480;    // [64][132]
    float* xS   = sm + 28928;    // [64][66]
    float* b1S  = sm + 33152;    // 64
    float* bihS = sm + 33216;    // 192

    const int tid = threadIdx.x;
    const int b0  = blockIdx.x * 64;
    const int t0  = blockIdx.y * 8;

    for (int i = tid; i < 128*64; i += 256){ int j = i & 63, k = i >> 6; W1T[k*64 + j] = W1[j*128 + k]; }
    for (int i = tid; i < 64*192; i += 256){ int g = i % 192, k = i / 192; WihT[k*192 + g] = Wih[g*64 + k]; }
    if (tid < 64)  b1S[tid]  = b1[tid];
    if (tid < 192) bihS[tid] = bih[tid];

    const int row = tid >> 2;   // 0..63
    const int sub = tid & 3;    // 0..3

    for (int tt = 0; tt < 8; tt++){
        const int t = t0 + tt;
        __syncthreads();
        for (int i = tid; i < 64*32; i += 256){
            int r = i >> 5, c = (i & 31) << 2;
            *(float4*)&sS[r*132 + c] = *(const float4*)&S[((size_t)(b0 + r)*T_ + t)*D_ + c];
        }
        __syncthreads();

        // phase A: x = relu(W1 @ s + b1); thread owns j = sub*16 .. +15
        ull xa[8];
        #pragma unroll
        for (int m = 0; m < 8; m++) xa[m] = *(const ull*)&b1S[sub*16 + 2*m];
        #pragma unroll 4
        for (int k = 0; k < 128; k++){
            ull s2 = splat2(sS[row*132 + k]);
            const ulonglong2* wp = (const ulonglong2*)&W1T[k*64 + sub*16];
            #pragma unroll
            for (int i = 0; i < 4; i++){
                ulonglong2 w = wp[i];
                xa[2*i]   = fma2(w.x, s2, xa[2*i]);
                xa[2*i+1] = fma2(w.y, s2, xa[2*i+1]);
            }
        }
        #pragma unroll
        for (int m = 0; m < 8; m++){
            float2 v = u2f(xa[m]);
            *(ull*)&xS[row*66 + sub*16 + 2*m] = f2u(fmaxf(v.x, 0.f), fmaxf(v.y, 0.f));
        }
        __syncwarp();   // xS row written/read by same 4 threads of one warp

        // phase B: gx = Wih @ x + bih; thread owns g = sub*48 .. +47
        ull ga[24];
        #pragma unroll
        for (int m = 0; m < 24; m++) ga[m] = *(const ull*)&bihS[sub*48 + 2*m];
        #pragma unroll 4
        for (int k = 0; k < 64; k++){
            ull x2 = splat2(xS[row*66 + k]);
            const ulonglong2* wp = (const ulonglong2*)&WihT[k*192 + sub*48];
            #pragma unroll
            for (int i = 0; i < 12; i++){
                ulonglong2 w = wp[i];
                ga[2*i]   = fma2(w.x, x2, ga[2*i]);
                ga[2*i+1] = fma2(w.y, x2, ga[2*i+1]);
            }
        }
        float* dst = &g_gx[((size_t)t*B_ + b0 + row)*G3_ + sub*48];
        #pragma unroll
        for (int j = 0; j < 12; j++){
            float2 a = u2f(ga[2*j]), b = u2f(ga[2*j+1]);
            *(float4*)&dst[4*j] = make_float4(a.x, a.y, b.x, b.y);
        }
    }
}

// ======================= Kernel B: GRU scan =================================
// 128 blocks x 16 rows. 192 threads = 96 gate-pairs (Whh rows in registers)
// x 2 pair-groups of 4 row-pairs. h pair-packed f32x2 in smem.
__global__ void __launch_bounds__(192, 1) scan_kernel(
    const float* __restrict__ Whh, const float* __restrict__ bhh,
    const float* __restrict__ Wout, const float* __restrict__ bout,
    float* __restrict__ out)
{
    __shared__ ull   h2s[8*64];       // [pair][hIdx], lanes = (row even, row odd)
    __shared__ ull   ghS[8*192];      // [pair][gate]
    __shared__ float gxS[2][16*192];  // double-buffered gx staging

    const int tid = threadIdx.x;
    const int gp  = tid % 96;         // gates 2gp, 2gp+1
    const int pg  = tid / 96;         // row-pairs pg*4 .. pg*4+3
    const int b0  = blockIdx.x * 16;

    float w0[64], w1[64];
    #pragma unroll 8
    for (int k = 0; k < 64; k++){ w0[k] = Whh[(2*gp)*64 + k]; w1[k] = Whh[(2*gp+1)*64 + k]; }
    const float bh0 = bhh[2*gp], bh1 = bhh[2*gp+1];

    for (int i = tid; i < 512; i += 192) h2s[i] = 0;
    for (int i = tid; i < 768; i += 192){
        int r = i / 48, c = (i % 48) << 2;
        *(float4*)&gxS[0][r*192 + c] = *(const float4*)&g_gx[((size_t)(b0 + r))*G3_ + c];
    }
    __syncthreads();

    for (int t = 0; t < T_; t++){
        const int cb = t & 1;
        if (t + 1 < T_){
            const float* src = &g_gx[((size_t)(t+1)*B_ + b0)*G3_];
            float* dst = gxS[cb ^ 1];
            for (int i = tid; i < 768; i += 192){
                int r = i / 48, c = (i % 48) << 2;
                *(float4*)&dst[r*192 + c] = *(const float4*)&src[r*192 + c];
            }
        }
        // compute gh = Whh @ h + bhh for 4 row-pairs, 2 gates
        ull acc[8];
        #pragma unroll
        for (int rp = 0; rp < 4; rp++){ acc[2*rp] = splat2(bh0); acc[2*rp+1] = splat2(bh1); }
        const ull* hp = &h2s[pg*4*64];
        #pragma unroll
        for (int k = 0; k < 64; k++){
            ull ws0 = splat2(w0[k]), ws1 = splat2(w1[k]);
            #pragma unroll
            for (int rp = 0; rp < 4; rp++){
                ull h2 = hp[rp*64 + k];
                acc[2*rp]   = fma2(ws0, h2, acc[2*rp]);
                acc[2*rp+1] = fma2(ws1, h2, acc[2*rp+1]);
            }
        }
        #pragma unroll
        for (int rp = 0; rp < 4; rp++){
            ghS[(pg*4+rp)*192 + 2*gp]     = acc[2*rp];
            ghS[(pg*4+rp)*192 + 2*gp + 1] = acc[2*rp+1];
        }
        __syncthreads();

        // gate phase: 512 (pair,hIdx) updates
        for (int i = tid; i < 512; i += 192){
            int pair = i >> 6, hI = i & 63;
            const float* ga = &gxS[cb][(2*pair)*192];
            const float* gb = ga + 192;
            float2 R = u2f(ghS[pair*192 + hI]);
            float2 Z = u2f(ghS[pair*192 + 64 + hI]);
            float2 N = u2f(ghS[pair*192 + 128 + hI]);
            float2 h = u2f(h2s[pair*64 + hI]);
            float ra = sig_(ga[hI] + R.x),      rb = sig_(gb[hI] + R.y);
            float za = sig_(ga[64+hI] + Z.x),   zb = sig_(gb[64+hI] + Z.y);
            float na = tanh_(ga[128+hI] + ra*N.x), nb = tanh_(gb[128+hI] + rb*N.y);
            float ha = (1.f - za)*na + za*h.x;
            float hb = (1.f - zb)*nb + zb*h.y;
            h2s[pair*64 + hI] = f2u(ha, hb);
        }
        __syncthreads();
    }

    if (tid < 16){
        int pair = tid >> 1, lane = tid & 1;
        float acc = bout[0];
        #pragma unroll 8
        for (int k = 0; k < 64; k++){
            float2 h = u2f(h2s[pair*64 + k]);
            acc += Wout[k] * (lane ? h.y : h.x);
        }
        out[b0 + tid] = acc;
    }
}

extern "C" void kernel_launch(void* const* d_in, const int* in_sizes, int n_in,
                              void* d_out, int out_size)
{
    const float* S    = (const float*)d_in[0];
    const float* W1   = (const float*)d_in[1];
    const float* b1   = (const float*)d_in[2];
    const float* Wih  = (const float*)d_in[3];
    const float* Whh  = (const float*)d_in[4];
    const float* bih  = (const float*)d_in[5];
    const float* bhh  = (const float*)d_in[6];
    const float* Wout = (const float*)d_in[7];
    const float* bout = (const float*)d_in[8];
    float* out = (float*)d_out;

    cudaFuncSetAttribute(ff_kernel, cudaFuncAttributeMaxDynamicSharedMemorySize, 133632);
    ff_kernel<<<dim3(32, 64), 256, 133632>>>(S, W1, b1, Wih, bih);
    scan_kernel<<<128, 192>>>(Whh, bhh, Wout, bout, out);
}

// round 16
// speedup vs baseline: 1.7379x; 1.7379x over previous
#include <cuda_runtime.h>

#define B_  2048
#define T_  512
#define D_  128
#define G3_ 192

typedef unsigned long long ull;

__device__ __align__(256) float g_gx[(size_t)T_ * B_ * G3_];  // [T][B][192]

__device__ __forceinline__ ull splat2(float x){ ull r; asm("mov.b64 %0, {%1, %1};" : "=l"(r) : "f"(x)); return r; }
__device__ __forceinline__ ull fma2(ull a, ull b, ull c){ ull d; asm("fma.rn.f32x2 %0, %1, %2, %3;" : "=l"(d) : "l"(a), "l"(b), "l"(c)); return d; }
__device__ __forceinline__ float2 u2f(ull v){ float2 f; asm("mov.b64 {%0, %1}, %2;" : "=f"(f.x), "=f"(f.y) : "l"(v)); return f; }
__device__ __forceinline__ ull f2u(float x, float y){ ull r; asm("mov.b64 %0, {%1, %2};" : "=l"(r) : "f"(x), "f"(y)); return r; }
__device__ __forceinline__ float tanh_(float x){ float y; asm("tanh.approx.f32 %0, %1;" : "=f"(y) : "f"(x)); return y; }
__device__ __forceinline__ float sig_(float x){ return fmaf(0.5f, tanh_(0.5f * x), 0.5f); }

// ======================= Kernel A: feedforward ==============================
// gx = Wih @ relu(W1 @ s + b1) + bih.  Block: 64 batch rows x 8 timesteps.
// Thread tile: 2 rows x (8 j / 24 gates). 256 threads, register-tiled GEMMs.
__global__ void __launch_bounds__(256) ff_kernel(
    const float* __restrict__ S, const float* __restrict__ W1,
    const float* __restrict__ b1, const float* __restrict__ Wih,
    const float* __restrict__ bih)
{
    extern __shared__ float sm[];
    float* W1T  = sm;            // [128][64]   8192
    float* WihT = sm + 8192;     // [64][192]   12288
    float* sS   = sm + 20480;    // [64][132]   8448
    float* xS   = sm + 28928;    // [64][68]    4352
    float* b1S  = sm + 33280;    // 64
    float* bihS = sm + 33344;    // 192  (end 33536 floats = 134144 B)

    const int tid = threadIdx.x;
    const int b0  = blockIdx.x * 64;
    const int t0  = blockIdx.y * 8;

    for (int i = tid; i < 128*64; i += 256){ int j = i & 63, k = i >> 6; W1T[k*64 + j] = W1[j*128 + k]; }
    for (int i = tid; i < 64*192; i += 256){ int g = i % 192, k = i / 192; WihT[k*192 + g] = Wih[g*64 + k]; }
    if (tid < 64)  b1S[tid]  = b1[tid];
    if (tid < 192) bihS[tid] = bih[tid];

    const int rg   = tid >> 3;       // 0..31 -> rows rg*2, rg*2+1
    const int cg   = tid & 7;        // 0..7
    const int row0 = rg * 2;

    for (int tt = 0; tt < 8; tt++){
        const int t = t0 + tt;
        __syncthreads();
        for (int i = tid; i < 64*32; i += 256){
            int r = i >> 5, c = (i & 31) << 2;
            *(float4*)&sS[r*132 + c] = *(const float4*)&S[((size_t)(b0 + r)*T_ + t)*D_ + c];
        }
        __syncthreads();

        // ---- GEMM1: x = relu(W1 @ s + b1); thread: 2 rows x j=cg*8..+7 ----
        ull xa[2][4];
        #pragma unroll
        for (int m = 0; m < 4; m++){
            ull bb = *(const ull*)&b1S[cg*8 + 2*m];
            xa[0][m] = bb; xa[1][m] = bb;
        }
        const float* s0p = &sS[row0*132];
        const float* s1p = s0p + 132;
        #pragma unroll 4
        for (int k = 0; k < 128; k++){
            ull s0 = splat2(s0p[k]);
            ull s1 = splat2(s1p[k]);
            ulonglong2 wA = *(const ulonglong2*)&W1T[k*64 + cg*8];
            ulonglong2 wB = *(const ulonglong2*)&W1T[k*64 + cg*8 + 4];
            xa[0][0] = fma2(wA.x, s0, xa[0][0]); xa[0][1] = fma2(wA.y, s0, xa[0][1]);
            xa[0][2] = fma2(wB.x, s0, xa[0][2]); xa[0][3] = fma2(wB.y, s0, xa[0][3]);
            xa[1][0] = fma2(wA.x, s1, xa[1][0]); xa[1][1] = fma2(wA.y, s1, xa[1][1]);
            xa[1][2] = fma2(wB.x, s1, xa[1][2]); xa[1][3] = fma2(wB.y, s1, xa[1][3]);
        }
        #pragma unroll
        for (int r = 0; r < 2; r++){
            float2 v0 = u2f(xa[r][0]), v1 = u2f(xa[r][1]);
            float2 v2 = u2f(xa[r][2]), v3 = u2f(xa[r][3]);
            float* xd = &xS[(row0 + r)*68 + cg*8];
            *(float4*)&xd[0] = make_float4(fmaxf(v0.x,0.f), fmaxf(v0.y,0.f), fmaxf(v1.x,0.f), fmaxf(v1.y,0.f));
            *(float4*)&xd[4] = make_float4(fmaxf(v2.x,0.f), fmaxf(v2.y,0.f), fmaxf(v3.x,0.f), fmaxf(v3.y,0.f));
        }
        __syncwarp();   // x rows written and read within the same warp (8 threads per rg)

        // ---- GEMM2: gx = Wih @ x + bih; thread: 2 rows x gates cg*24..+23 ----
        ull ga[2][12];
        #pragma unroll
        for (int m = 0; m < 12; m++){
            ull bb = *(const ull*)&bihS[cg*24 + 2*m];
            ga[0][m] = bb; ga[1][m] = bb;
        }
        const float* x0p = &xS[row0*68];
        const float* x1p = x0p + 68;
        #pragma unroll 4
        for (int k = 0; k < 64; k++){
            ull x0 = splat2(x0p[k]);
            ull x1 = splat2(x1p[k]);
            const ulonglong2* wp = (const ulonglong2*)&WihT[k*192 + cg*24];
            #pragma unroll
            for (int i = 0; i < 6; i++){
                ulonglong2 w = wp[i];
                ga[0][2*i]   = fma2(w.x, x0, ga[0][2*i]);
                ga[0][2*i+1] = fma2(w.y, x0, ga[0][2*i+1]);
                ga[1][2*i]   = fma2(w.x, x1, ga[1][2*i]);
                ga[1][2*i+1] = fma2(w.y, x1, ga[1][2*i+1]);
            }
        }
        #pragma unroll
        for (int r = 0; r < 2; r++){
            float* dst = &g_gx[((size_t)t*B_ + b0 + row0 + r)*G3_ + cg*24];
            #pragma unroll
            for (int j = 0; j < 6; j++){
                float2 a = u2f(ga[r][2*j]), b = u2f(ga[r][2*j+1]);
                *(float4*)&dst[4*j] = make_float4(a.x, a.y, b.x, b.y);
            }
        }
    }
}

// ======================= Kernel B: GRU scan =================================
// 128 blocks x 16 rows, 384 threads (12 warps = 3/SMSP).
// Thread: 2 gates (Whh pair-packed in 64 ull regs) x 4 rows.
// h stored PRE-SPLATTED in smem -> gh inner loop = 2 LDS.128 + 4 fma2 per k.
__global__ void __launch_bounds__(384, 1) scan_kernel(
    const float* __restrict__ Whh, const float* __restrict__ bhh,
    const float* __restrict__ Wout, const float* __restrict__ bout,
    float* __restrict__ out)
{
    __shared__ ull   hs[64*20];        // [k][row(+pad)] splatted h: (h,h)
    __shared__ ull   ghS[96*18];       // [gate-pair][row(+pad)]
    __shared__ float gxS[2][16*196];   // double-buffered gx staging, padded rows

    const int tid = threadIdx.x;
    const int gp  = tid % 96;          // gates 2gp, 2gp+1
    const int rg  = tid / 96;          // 0..3 -> rows rg*4 .. rg*4+3
    const int b0  = blockIdx.x * 16;

    // pack Whh rows 2gp, 2gp+1 column-wise into register ulls
    ull wp[64];
    #pragma unroll
    for (int q = 0; q < 16; q++){
        float4 a = *(const float4*)&Whh[(2*gp)*64 + q*4];
        float4 b = *(const float4*)&Whh[(2*gp+1)*64 + q*4];
        wp[4*q+0] = f2u(a.x, b.x); wp[4*q+1] = f2u(a.y, b.y);
        wp[4*q+2] = f2u(a.z, b.z); wp[4*q+3] = f2u(a.w, b.w);
    }
    const ull bh = f2u(bhh[2*gp], bhh[2*gp+1]);

    for (int i = tid; i < 64*20; i += 384) hs[i] = 0;
    for (int i = tid; i < 768; i += 384){
        int r = i / 48, c = (i % 48) << 2;
        *(float4*)&gxS[0][r*196 + c] = *(const float4*)&g_gx[((size_t)(b0 + r))*G3_ + c];
    }
    __syncthreads();

    const int pr0 = tid / 48, pc0 = (tid % 48) << 2;
    const int i2  = tid + 384;
    const int pr1 = i2 / 48,  pc1 = (i2 % 48) << 2;

    for (int t = 0; t < T_; t++){
        const int cb = t & 1;
        // prefetch gx(t+1) into registers
        float4 pf0, pf1;
        const bool hasPf = (t + 1 < T_);
        if (hasPf){
            const float* src = &g_gx[((size_t)(t+1)*B_ + b0)*G3_];
            pf0 = *(const float4*)&src[pr0*192 + pc0];
            pf1 = *(const float4*)&src[pr1*192 + pc1];
        }

        // gh = Whh @ h + bhh  (2 gates x 4 rows)
        ull acc0 = bh, acc1 = bh, acc2 = bh, acc3 = bh;
        #pragma unroll
        for (int k = 0; k < 64; k++){
            ulonglong2 hA = *(const ulonglong2*)&hs[k*20 + rg*4];
            ulonglong2 hB = *(const ulonglong2*)&hs[k*20 + rg*4 + 2];
            ull w = wp[k];
            acc0 = fma2(w, hA.x, acc0);
            acc1 = fma2(w, hA.y, acc1);
            acc2 = fma2(w, hB.x, acc2);
            acc3 = fma2(w, hB.y, acc3);
        }
        {
            ull* gh = &ghS[gp*18 + rg*4];
            gh[0] = acc0; gh[1] = acc1; gh[2] = acc2; gh[3] = acc3;
        }
        if (hasPf){
            float* dst = gxS[cb ^ 1];
            *(float4*)&dst[pr0*196 + pc0] = pf0;
            *(float4*)&dst[pr1*196 + pc1] = pf1;
        }
        __syncthreads();

        // gate phase: 512 items = (gate-index-pair hp, row r)
        const float* hf = (const float*)hs;
        for (int it = tid; it < 512; it += 384){
            int hp = it >> 4, r = it & 15;
            float2 R = u2f(ghS[hp*18 + r]);
            float2 Z = u2f(ghS[(32 + hp)*18 + r]);
            float2 N = u2f(ghS[(64 + hp)*18 + r]);
            const float* gb = &gxS[cb][r*196];
            float2 gr = *(const float2*)&gb[2*hp];
            float2 gz = *(const float2*)&gb[64 + 2*hp];
            float2 gn = *(const float2*)&gb[128 + 2*hp];
            float h0 = hf[((2*hp)*20 + r)*2];
            float h1 = hf[((2*hp+1)*20 + r)*2];
            float r0 = sig_(gr.x + R.x), r1 = sig_(gr.y + R.y);
            float z0 = sig_(gz.x + Z.x), z1 = sig_(gz.y + Z.y);
            float n0 = tanh_(gn.x + r0*N.x), n1 = tanh_(gn.y + r1*N.y);
            h0 = (1.f - z0)*n0 + z0*h0;
            h1 = (1.f - z1)*n1 + z1*h1;
            hs[(2*hp)*20   + r] = f2u(h0, h0);
            hs[(2*hp+1)*20 + r] = f2u(h1, h1);
        }
        __syncthreads();
    }

    if (tid < 16){
        float acc = bout[0];
        #pragma unroll 8
        for (int k = 0; k < 64; k++)
            acc += Wout[k] * ((const float*)&hs[k*20 + tid])[0];
        out[b0 + tid] = acc;
    }
}

extern "C" void kernel_launch(void* const* d_in, const int* in_sizes, int n_in,
                              void* d_out, int out_size)
{
    const float* S    = (const float*)d_in[0];
    const float* W1   = (const float*)d_in[1];
    const float* b1   = (const float*)d_in[2];
    const float* Wih  = (const float*)d_in[3];
    const float* Whh  = (const float*)d_in[4];
    const float* bih  = (const float*)d_in[5];
    const float* bhh  = (const float*)d_in[6];
    const float* Wout = (const float*)d_in[7];
    const float* bout = (const float*)d_in[8];
    float* out = (float*)d_out;

    cudaFuncSetAttribute(ff_kernel, cudaFuncAttributeMaxDynamicSharedMemorySize, 134144);
    ff_kernel<<<dim3(32, 64), 256, 134144>>>(S, W1, b1, Wih, bih);
    scan_kernel<<<128, 384>>>(Whh, bhh, Wout, bout, out);
}